// round 13
// baseline (speedup 1.0000x reference)
#include <cuda_runtime.h>
#include <cstdint>

#define NROWS 32768
#define KCODES 8192
#define DD 256
#define QSIZE (NROWS * DD)

#define MT 128                 // rows per unit (block M tile)
#define NT 128                 // codes per n-tile
#define NSEG 2048              // codes per work unit
#define KC 32                  // k per streamed B chunk
#define NUNITS ((NROWS / MT) * (KCODES / NSEG))       // 1024
#define NTPU (NSEG / NT)                              // 16 n-tiles per unit
#define KCH (DD / KC)                                 // 8 k-chunks
#define CPU (NTPU * KCH)                              // 128 chunks per unit

// ---- device scratch ----
__device__ unsigned long long g_best[NROWS];
__device__ float g_zz[NROWS];
__device__ float g_ee[KCODES];
__device__ float g_partial[8192];
__device__ int   g_work;

#define FFMA2(acc, a, b) asm("fma.rn.f32x2 %0, %1, %2, %0;" : "+l"(acc) : "l"(a), "l"(b))
#define UNPK(lo, hi, v) asm("mov.b64 {%0, %1}, %2;" : "=f"(lo), "=f"(hi) : "l"(v))

// -------- fused init + row squared-norms for z and codebook (one launch) --------
__global__ void vq_prep_kernel(const float* __restrict__ z, const float* __restrict__ cb) {
    int w = (blockIdx.x * blockDim.x + threadIdx.x) >> 5;
    int lane = threadIdx.x & 31;
    if (w == 0 && lane == 0) g_work = 0;
    const float* row;
    float* dst;
    if (w < NROWS) {
        if (lane == 0) g_best[w] = 0xFFFFFFFFFFFFFFFFULL;
        row = z + (size_t)w * DD;
        dst = &g_zz[w];
    } else {
        int c = w - NROWS;
        if (c >= KCODES) return;
        row = cb + (size_t)c * DD;
        dst = &g_ee[c];
    }
    float s = 0.f;
#pragma unroll
    for (int j = 0; j < DD / 32; j++) {
        float v = row[lane + 32 * j];
        s = fmaf(v, v, s);
    }
#pragma unroll
    for (int o = 16; o; o >>= 1) s += __shfl_xor_sync(0xffffffffu, s, o);
    if (lane == 0) *dst = s;
}

// -------- main distance-argmin kernel (FFMA2 engine, dup-pair B smem) --------
// 256 threads = 16 tx (codes) x 16 ty (row-groups). Thread tile: 8 rows x 8 codes.
// A tile (128 rows x 256 k) smem-resident, transposed [k][m] + xor swizzle (as R2/R12).
// B streamed in [KC=32][128] chunks stored as DUPLICATED (v,v) pairs: 8B per value,
// chunk-of-16B layout with ch = (cb16 + (k>>2)) & 63 rotation (conflict-free loads).
__global__ void __launch_bounds__(256, 1) vq_argmin_kernel(
    const float* __restrict__ z, const float* __restrict__ cb) {
    extern __shared__ float smem[];
    float* At = smem;                        // 256*128 floats = 128 KB
    float* Bb0 = smem + DD * 128;            // 32*256 floats = 32 KB (dup pairs)
    float* Bb1 = Bb0 + KC * 256;             // 32 KB
    __shared__ int s_u;

    const int tid = threadIdx.x;
    const int tx = tid & 15;
    const int ty = tid >> 4;

    // loader indices
    const int akg = tid & 63;               // A: k-group (k/4), 0..63
    const int am0 = tid >> 6;               // A: base column (row), +4i
    const int bnb = tid >> 3;               // B: base code, +32i
    const int bk4 = tid & 7;                // B: k-group within chunk (k>>2)

    const float4* zg = reinterpret_cast<const float4*>(z);
    const float4* cg = reinterpret_cast<const float4*>(cb);

    for (;;) {
        if (tid == 0) s_u = atomicAdd(&g_work, 1);
        __syncthreads();                    // also fences prior unit's smem reads
        const int u = s_u;
        if (u >= NUNITS) return;

        const int rb = u & ((NROWS / MT) - 1);
        const int nseg = u >> 8;
        const int row0 = rb * MT;
        const int cseg0 = nseg * NSEG;

        // ---- load A tile: z[row0..+127][0..255] -> transposed+swizzled smem ----
        {
            const int s = akg & 7;
#pragma unroll
            for (int i = 0; i < 32; i++) {
                const int m = am0 + 4 * i;
                float4 v = zg[(size_t)(row0 + m) * 64 + akg];
                const int colg = (m >> 2) ^ s;
                float* dst = At + (akg * 4) * 128 + (colg << 2) + (m & 3);
                dst[0]   = v.x;
                dst[128] = v.y;
                dst[256] = v.z;
                dst[384] = v.w;
            }
        }

        // ---- prefetch B chunk 0 (codes cseg0..+127, k 0..31) ----
        float4 pf[4];
#pragma unroll
        for (int i = 0; i < 4; i++)
            pf[i] = cg[(size_t)(cseg0 + bnb + 32 * i) * 64 + bk4];

        __syncthreads();                    // A tile visible

        // commit chunk 0 into Bb0 (duplicated-pair layout)
        {
            float* dstb = Bb0;
#pragma unroll
            for (int i = 0; i < 4; i++) {
                const int n = bnb + 32 * i;
                const int h = n >> 6, cl = n & 63, tq = cl >> 2, r = cl & 3;
                const int ch = ((32 * h + 16 * (r >> 1) + tq) + bk4) & 63;
                float* p = dstb + (bk4 * 4) * 256 + ch * 4 + (r & 1) * 2;
                *reinterpret_cast<float2*>(p + 0)   = make_float2(pf[i].x, pf[i].x);
                *reinterpret_cast<float2*>(p + 256) = make_float2(pf[i].y, pf[i].y);
                *reinterpret_cast<float2*>(p + 512) = make_float2(pf[i].z, pf[i].z);
                *reinterpret_cast<float2*>(p + 768) = make_float2(pf[i].w, pf[i].w);
            }
        }
        __syncthreads();

        // per-row argmin state (8 rows per thread), zz cached
        float bd[8];
        int   bk[8];
        float zzr[8];
#pragma unroll
        for (int r = 0; r < 8; r++) {
            bd[r] = __int_as_float(0x7f800000);
            bk[r] = 0;
            zzr[r] = g_zz[row0 + ty * 8 + r];
        }

        int buf = 0;
        for (int nt = 0; nt < NTPU; nt++) {
            // 32 b64 accumulators: 4 row-pairs x 8 codes
            unsigned long long acc[4][8];
#pragma unroll
            for (int p = 0; p < 4; p++)
#pragma unroll
                for (int c = 0; c < 8; c++) acc[p][c] = 0ULL;

            for (int kc = 0; kc < KCH; kc++) {
                const int ci = nt * KCH + kc;
                const bool more = (ci + 1 < CPU);

                // prefetch next B chunk into registers
                if (more) {
                    const int nt2 = (ci + 1) >> 3;
                    const int kc2 = (ci + 1) & 7;
                    const size_t cb0 = (size_t)(cseg0 + nt2 * NT);
#pragma unroll
                    for (int i = 0; i < 4; i++)
                        pf[i] = cg[(cb0 + bnb + 32 * i) * 64 + (kc2 * 8 + bk4)];
                }

                // ---- compute current chunk ----
                const float* Ac = At + kc * KC * 128;
                const float* Bc = buf ? Bb1 : Bb0;
#pragma unroll 4
                for (int ks = 0; ks < 8; ks++) {
                    const int oa0 = (((2 * ty)     ^ ks) << 2);
                    const int oa1 = (((2 * ty + 1) ^ ks) << 2);
                    const int ob0 = ((tx + ks) & 63) << 2;
                    const int ob1 = ((16 + tx + ks) & 63) << 2;
                    const int ob2 = ((32 + tx + ks) & 63) << 2;
                    const int ob3 = ((48 + tx + ks) & 63) << 2;
                    const float* Ak = Ac + ks * 4 * 128;
                    const float* Bk = Bc + ks * 4 * 256;
#pragma unroll
                    for (int j = 0; j < 4; j++) {
                        ulonglong2 a01 = *reinterpret_cast<const ulonglong2*>(Ak + j * 128 + oa0);
                        ulonglong2 a23 = *reinterpret_cast<const ulonglong2*>(Ak + j * 128 + oa1);
                        ulonglong2 q0 = *reinterpret_cast<const ulonglong2*>(Bk + j * 256 + ob0);
                        ulonglong2 q1 = *reinterpret_cast<const ulonglong2*>(Bk + j * 256 + ob1);
                        ulonglong2 q2 = *reinterpret_cast<const ulonglong2*>(Bk + j * 256 + ob2);
                        ulonglong2 q3 = *reinterpret_cast<const ulonglong2*>(Bk + j * 256 + ob3);

                        FFMA2(acc[0][0], a01.x, q0.x); FFMA2(acc[1][0], a01.y, q0.x);
                        FFMA2(acc[2][0], a23.x, q0.x); FFMA2(acc[3][0], a23.y, q0.x);
                        FFMA2(acc[0][1], a01.x, q0.y); FFMA2(acc[1][1], a01.y, q0.y);
                        FFMA2(acc[2][1], a23.x, q0.y); FFMA2(acc[3][1], a23.y, q0.y);
                        FFMA2(acc[0][2], a01.x, q1.x); FFMA2(acc[1][2], a01.y, q1.x);
                        FFMA2(acc[2][2], a23.x, q1.x); FFMA2(acc[3][2], a23.y, q1.x);
                        FFMA2(acc[0][3], a01.x, q1.y); FFMA2(acc[1][3], a01.y, q1.y);
                        FFMA2(acc[2][3], a23.x, q1.y); FFMA2(acc[3][3], a23.y, q1.y);
                        FFMA2(acc[0][4], a01.x, q2.x); FFMA2(acc[1][4], a01.y, q2.x);
                        FFMA2(acc[2][4], a23.x, q2.x); FFMA2(acc[3][4], a23.y, q2.x);
                        FFMA2(acc[0][5], a01.x, q2.y); FFMA2(acc[1][5], a01.y, q2.y);
                        FFMA2(acc[2][5], a23.x, q2.y); FFMA2(acc[3][5], a23.y, q2.y);
                        FFMA2(acc[0][6], a01.x, q3.x); FFMA2(acc[1][6], a01.y, q3.x);
                        FFMA2(acc[2][6], a23.x, q3.x); FFMA2(acc[3][6], a23.y, q3.x);
                        FFMA2(acc[0][7], a01.x, q3.y); FFMA2(acc[1][7], a01.y, q3.y);
                        FFMA2(acc[2][7], a23.x, q3.y); FFMA2(acc[3][7], a23.y, q3.y);
                    }
                }

                // commit prefetched chunk into the other buffer (dup-pair layout)
                if (more) {
                    float* dstb = buf ? Bb0 : Bb1;
#pragma unroll
                    for (int i = 0; i < 4; i++) {
                        const int n = bnb + 32 * i;
                        const int h = n >> 6, cl = n & 63, tq = cl >> 2, r = cl & 3;
                        const int ch = ((32 * h + 16 * (r >> 1) + tq) + bk4) & 63;
                        float* p = dstb + (bk4 * 4) * 256 + ch * 4 + (r & 1) * 2;
                        *reinterpret_cast<float2*>(p + 0)   = make_float2(pf[i].x, pf[i].x);
                        *reinterpret_cast<float2*>(p + 256) = make_float2(pf[i].y, pf[i].y);
                        *reinterpret_cast<float2*>(p + 512) = make_float2(pf[i].z, pf[i].z);
                        *reinterpret_cast<float2*>(p + 768) = make_float2(pf[i].w, pf[i].w);
                    }
                }
                __syncthreads();
                buf ^= 1;
            }

            // ---- epilogue: d = (zz + ee) - 2*s, first-index argmin ----
            const int cbase = cseg0 + nt * NT;
#pragma unroll
            for (int g = 0; g < 2; g++) {
#pragma unroll
                for (int cc = 0; cc < 4; cc++) {
                    const int code = cbase + g * 64 + tx * 4 + cc;
                    const float ee = __ldg(&g_ee[code]);
                    const int ci = g * 4 + cc;
#pragma unroll
                    for (int p = 0; p < 4; p++) {
                        float lo, hi;
                        UNPK(lo, hi, acc[p][ci]);
                        const float dlo = (zzr[2 * p]     + ee) - 2.0f * lo;
                        const float dhi = (zzr[2 * p + 1] + ee) - 2.0f * hi;
                        if (dlo < bd[2 * p])     { bd[2 * p] = dlo;     bk[2 * p] = code; }
                        if (dhi < bd[2 * p + 1]) { bd[2 * p + 1] = dhi; bk[2 * p + 1] = code; }
                    }
                }
            }
        }

        // ---- reduce across 16 tx lanes, then global atomic merge ----
#pragma unroll
        for (int r = 0; r < 8; r++) {
            float d = bd[r];
            int   k = bk[r];
#pragma unroll
            for (int o = 1; o < 16; o <<= 1) {
                float od = __shfl_xor_sync(0xffffffffu, d, o);
                int   ok = __shfl_xor_sync(0xffffffffu, k, o);
                if (od < d || (od == d && ok < k)) { d = od; k = ok; }
            }
            if (tx == 0) {
                unsigned long long key =
                    ((unsigned long long)__float_as_uint(d) << 32) | (unsigned int)k;
                atomicMin(&g_best[row0 + ty * 8 + r], key);
            }
        }
    }
}

// -------- output gather + straight-through + loss partials --------
__global__ void vq_output_kernel(const float* __restrict__ z, const float* __restrict__ cb,
                                 float* __restrict__ out) {
    const int tid = threadIdx.x;
    const size_t g4 = (size_t)blockIdx.x * 256 + tid;
    const int row = (int)(g4 >> 6);
    const int c4 = (int)(g4 & 63);
    const int idx = (int)(g_best[row] & 0xFFFFFFFFULL);

    const float4 zv = reinterpret_cast<const float4*>(z)[g4];
    const float4 qv = reinterpret_cast<const float4*>(cb)[(size_t)idx * 64 + c4];

    float4 o;
    o.x = zv.x + (qv.x - zv.x);
    o.y = zv.y + (qv.y - zv.y);
    o.z = zv.z + (qv.z - zv.z);
    o.w = zv.w + (qv.w - zv.w);
    reinterpret_cast<float4*>(out)[g4] = o;

    const float dx = zv.x - qv.x, dy = zv.y - qv.y, dz = zv.z - qv.z, dw = zv.w - qv.w;
    float part = dx * dx;
    part = fmaf(dy, dy, part);
    part = fmaf(dz, dz, part);
    part = fmaf(dw, dw, part);

    __shared__ float sp[256];
    sp[tid] = part;
    __syncthreads();
#pragma unroll
    for (int s = 128; s; s >>= 1) {
        if (tid < s) sp[tid] += sp[tid + s];
        __syncthreads();
    }
    if (tid == 0) g_partial[blockIdx.x] = sp[0];
}

// -------- deterministic final loss reduction --------
__global__ void vq_loss_kernel(float* __restrict__ out, int out_size) {
    __shared__ double sm[256];
    const int tid = threadIdx.x;
    double s = 0.0;
    for (int i = tid; i < 8192; i += 256) s += (double)g_partial[i];
    sm[tid] = s;
    __syncthreads();
#pragma unroll
    for (int st = 128; st; st >>= 1) {
        if (tid < st) sm[tid] += sm[tid + st];
        __syncthreads();
    }
    if (tid == 0) {
        const float m = (float)(sm[0] / (double)QSIZE);
        const float vq = 0.25f * m + m;
        for (int i = QSIZE; i < out_size; i++) out[i] = vq;
    }
}

extern "C" void kernel_launch(void* const* d_in, const int* in_sizes, int n_in,
                              void* d_out, int out_size) {
    const float* z  = (const float*)d_in[0];
    const float* cb = (const float*)d_in[1];
    if (n_in >= 2 && in_sizes[0] == KCODES * DD && in_sizes[1] == NROWS * DD) {
        const float* t = z; z = cb; cb = t;
    }
    float* out = (float*)d_out;

    const int smem_bytes = (DD * 128 + 2 * KC * 256) * (int)sizeof(float);  // 196608
    cudaFuncSetAttribute(vq_argmin_kernel,
                         cudaFuncAttributeMaxDynamicSharedMemorySize, smem_bytes);

    vq_prep_kernel<<<((NROWS + KCODES) * 32) / 256, 256>>>(z, cb);
    vq_argmin_kernel<<<148, 256, smem_bytes>>>(z, cb);
    vq_output_kernel<<<QSIZE / 1024, 256>>>(z, cb, out);
    vq_loss_kernel<<<1, 256>>>(out, out_size);
}

// round 14
// speedup vs baseline: 1.1291x; 1.1291x over previous
#include <cuda_runtime.h>
#include <cstdint>

#define NROWS 32768
#define KCODES 8192
#define DD 256
#define QSIZE (NROWS * DD)

#define MT 128                 // rows per unit (block M tile)
#define NT 128                 // codes per n-tile
#define NSEG 2048              // codes per work unit
#define KC 32                  // k per streamed B chunk
#define NUNITS ((NROWS / MT) * (KCODES / NSEG))       // 1024
#define NTPU (NSEG / NT)                              // 16 n-tiles per unit
#define KCH (DD / KC)                                 // 8 k-chunks
#define CPU (NTPU * KCH)                              // 128 chunks per unit

// ---- device scratch ----
__device__ unsigned long long g_best[NROWS];
__device__ float g_zz[NROWS];
__device__ float g_ee[KCODES];
__device__ float g_partial[8192];
__device__ int   g_work;

#define DUPB(dst, s)  asm("mov.b64 %0, {%1, %1};" : "=l"(dst) : "f"(s))
#define FFMA2(acc, a, b) asm("fma.rn.f32x2 %0, %1, %2, %0;" : "+l"(acc) : "l"(a), "l"(b))
#define UNPK(lo, hi, v) asm("mov.b64 {%0, %1}, %2;" : "=f"(lo), "=f"(hi) : "l"(v))

// -------- fused init + row squared-norms for z and codebook (one launch) --------
// warp w: w < NROWS -> z row norm + g_best init; else codebook row norm.
// Exact sequential fmaf chains identical to the rel_err=0.0 path of every round.
__global__ void vq_prep_kernel(const float* __restrict__ z, const float* __restrict__ cb) {
    int w = (blockIdx.x * blockDim.x + threadIdx.x) >> 5;
    int lane = threadIdx.x & 31;
    if (w == 0 && lane == 0) g_work = 0;
    const float* row;
    float* dst;
    if (w < NROWS) {
        if (lane == 0) g_best[w] = 0xFFFFFFFFFFFFFFFFULL;
        row = z + (size_t)w * DD;
        dst = &g_zz[w];
    } else {
        int c = w - NROWS;
        if (c >= KCODES) return;
        row = cb + (size_t)c * DD;
        dst = &g_ee[c];
    }
    float s = 0.f;
#pragma unroll
    for (int j = 0; j < DD / 32; j++) {
        float v = row[lane + 32 * j];
        s = fmaf(v, v, s);
    }
#pragma unroll
    for (int o = 16; o; o >>= 1) s += __shfl_xor_sync(0xffffffffu, s, o);
    if (lane == 0) *dst = s;
}

// -------- main distance-argmin kernel (the 2494.5us R12 FFMA2 engine) --------
// 256 threads = 16 tx (codes) x 16 ty (row-groups). Thread tile: 8 rows x 8 codes.
// A tile (128 rows x 256 k) fully smem-resident, transposed [k][m] + swizzle.
// B streamed in [KC=32][128] transposed chunks, double-buffered.
// Swizzle: value (k, x) stored at k*128 + (((x>>2) ^ ((k>>2)&7))<<2) + (x&3).
__global__ void __launch_bounds__(256, 1) vq_argmin_kernel(
    const float* __restrict__ z, const float* __restrict__ cb) {
    extern __shared__ float smem[];
    float* At = smem;                       // 256*128 floats = 128 KB
    float* Bb0 = smem + DD * 128;           // 32*128 floats = 16 KB
    float* Bb1 = Bb0 + KC * 128;            // 16 KB
    __shared__ int s_u;

    const int tid = threadIdx.x;
    const int tx = tid & 15;
    const int ty = tid >> 4;

    // loader indices
    const int akg = tid & 63;               // A: k-group (k/4), 0..63
    const int am0 = tid >> 6;               // A: base column (row), +4i
    const int bnb = tid >> 3;               // B: base code col, +32i
    const int bk4 = tid & 7;                // B: k-group within chunk

    const float4* zg = reinterpret_cast<const float4*>(z);
    const float4* cg = reinterpret_cast<const float4*>(cb);

    for (;;) {
        if (tid == 0) s_u = atomicAdd(&g_work, 1);
        __syncthreads();                    // also fences prior unit's smem reads
        const int u = s_u;
        if (u >= NUNITS) return;

        const int rb = u & ((NROWS / MT) - 1);        // 0..255
        const int nseg = u >> 8;                      // 0..3
        const int row0 = rb * MT;
        const int cseg0 = nseg * NSEG;

        // ---- load A tile: z[row0..+127][0..255] -> transposed+swizzled smem ----
        {
            const int s = akg & 7;
#pragma unroll
            for (int i = 0; i < 32; i++) {
                const int m = am0 + 4 * i;
                float4 v = zg[(size_t)(row0 + m) * 64 + akg];
                const int colg = (m >> 2) ^ s;
                float* dst = At + (akg * 4) * 128 + (colg << 2) + (m & 3);
                dst[0]   = v.x;
                dst[128] = v.y;
                dst[256] = v.z;
                dst[384] = v.w;
            }
        }

        // ---- prefetch B chunk 0 (codes cseg0..+127, k 0..31) ----
        float4 pf[4];
#pragma unroll
        for (int i = 0; i < 4; i++)
            pf[i] = cg[(size_t)(cseg0 + bnb + 32 * i) * 64 + bk4];

        __syncthreads();                    // A tile visible

        // commit chunk 0 into Bb0
        {
            float* dstb = Bb0;
#pragma unroll
            for (int i = 0; i < 4; i++) {
                const int n = bnb + 32 * i;
                const int colg = (n >> 2) ^ bk4;
                float* p = dstb + (bk4 * 4) * 128 + (colg << 2) + (n & 3);
                p[0]   = pf[i].x;
                p[128] = pf[i].y;
                p[256] = pf[i].z;
                p[384] = pf[i].w;
            }
        }
        __syncthreads();

        // per-row argmin state (8 rows per thread), zz cached
        float bd[8];
        int   bk[8];
        float zzr[8];
#pragma unroll
        for (int r = 0; r < 8; r++) {
            bd[r] = __int_as_float(0x7f800000);
            bk[r] = 0;
            zzr[r] = g_zz[row0 + ty * 8 + r];
        }

        int buf = 0;
        for (int nt = 0; nt < NTPU; nt++) {
            // 32 b64 accumulators: 4 row-pairs x 8 codes
            unsigned long long acc[4][8];
#pragma unroll
            for (int p = 0; p < 4; p++)
#pragma unroll
                for (int c = 0; c < 8; c++) acc[p][c] = 0ULL;

            for (int kc = 0; kc < KCH; kc++) {
                const int ci = nt * KCH + kc;
                const bool more = (ci + 1 < CPU);

                // prefetch next B chunk into registers
                if (more) {
                    const int nt2 = (ci + 1) >> 3;
                    const int kc2 = (ci + 1) & 7;
                    const size_t cb0 = (size_t)(cseg0 + nt2 * NT);
#pragma unroll
                    for (int i = 0; i < 4; i++)
                        pf[i] = cg[(cb0 + bnb + 32 * i) * 64 + (kc2 * 8 + bk4)];
                }

                // ---- compute current chunk ----
                const float* Ac = At + kc * KC * 128;
                const float* Bc = buf ? Bb1 : Bb0;
#pragma unroll 4
                for (int ks = 0; ks < 8; ks++) {
                    const int oa0 = (((2 * ty)     ^ ks) << 2);
                    const int oa1 = (((2 * ty + 1) ^ ks) << 2);
                    const int ob0 = ((tx           ^ ks) << 2);
                    const int ob1 = (((16 + tx)    ^ ks) << 2);
                    const float* Ak = Ac + ks * 4 * 128;
                    const float* Bk = Bc + ks * 4 * 128;
#pragma unroll
                    for (int j = 0; j < 4; j++) {
                        ulonglong2 a01 = *reinterpret_cast<const ulonglong2*>(Ak + j * 128 + oa0);
                        ulonglong2 a23 = *reinterpret_cast<const ulonglong2*>(Ak + j * 128 + oa1);
                        float4 b0 = *reinterpret_cast<const float4*>(Bk + j * 128 + ob0);
                        float4 b1 = *reinterpret_cast<const float4*>(Bk + j * 128 + ob1);

                        unsigned long long d0, d1, d2, d3, d4, d5, d6, d7;
                        DUPB(d0, b0.x); DUPB(d1, b0.y); DUPB(d2, b0.z); DUPB(d3, b0.w);
                        DUPB(d4, b1.x); DUPB(d5, b1.y); DUPB(d6, b1.z); DUPB(d7, b1.w);

                        FFMA2(acc[0][0], a01.x, d0); FFMA2(acc[1][0], a01.y, d0);
                        FFMA2(acc[2][0], a23.x, d0); FFMA2(acc[3][0], a23.y, d0);
                        FFMA2(acc[0][1], a01.x, d1); FFMA2(acc[1][1], a01.y, d1);
                        FFMA2(acc[2][1], a23.x, d1); FFMA2(acc[3][1], a23.y, d1);
                        FFMA2(acc[0][2], a01.x, d2); FFMA2(acc[1][2], a01.y, d2);
                        FFMA2(acc[2][2], a23.x, d2); FFMA2(acc[3][2], a23.y, d2);
                        FFMA2(acc[0][3], a01.x, d3); FFMA2(acc[1][3], a01.y, d3);
                        FFMA2(acc[2][3], a23.x, d3); FFMA2(acc[3][3], a23.y, d3);
                        FFMA2(acc[0][4], a01.x, d4); FFMA2(acc[1][4], a01.y, d4);
                        FFMA2(acc[2][4], a23.x, d4); FFMA2(acc[3][4], a23.y, d4);
                        FFMA2(acc[0][5], a01.x, d5); FFMA2(acc[1][5], a01.y, d5);
                        FFMA2(acc[2][5], a23.x, d5); FFMA2(acc[3][5], a23.y, d5);
                        FFMA2(acc[0][6], a01.x, d6); FFMA2(acc[1][6], a01.y, d6);
                        FFMA2(acc[2][6], a23.x, d6); FFMA2(acc[3][6], a23.y, d6);
                        FFMA2(acc[0][7], a01.x, d7); FFMA2(acc[1][7], a01.y, d7);
                        FFMA2(acc[2][7], a23.x, d7); FFMA2(acc[3][7], a23.y, d7);
                    }
                }

                // commit prefetched chunk into the other buffer
                if (more) {
                    float* dstb = buf ? Bb0 : Bb1;
#pragma unroll
                    for (int i = 0; i < 4; i++) {
                        const int n = bnb + 32 * i;
                        const int colg = (n >> 2) ^ bk4;
                        float* p = dstb + (bk4 * 4) * 128 + (colg << 2) + (n & 3);
                        p[0]   = pf[i].x;
                        p[128] = pf[i].y;
                        p[256] = pf[i].z;
                        p[384] = pf[i].w;
                    }
                }
                __syncthreads();
                buf ^= 1;
            }

            // ---- epilogue: d = (zz + ee) - 2*s, first-index argmin ----
            const int cbase = cseg0 + nt * NT;
#pragma unroll
            for (int g = 0; g < 2; g++) {
#pragma unroll
                for (int cc = 0; cc < 4; cc++) {
                    const int code = cbase + g * 64 + tx * 4 + cc;
                    const float ee = __ldg(&g_ee[code]);
                    const int ci = g * 4 + cc;
#pragma unroll
                    for (int p = 0; p < 4; p++) {
                        float lo, hi;
                        UNPK(lo, hi, acc[p][ci]);
                        const float dlo = (zzr[2 * p]     + ee) - 2.0f * lo;
                        const float dhi = (zzr[2 * p + 1] + ee) - 2.0f * hi;
                        if (dlo < bd[2 * p])     { bd[2 * p] = dlo;     bk[2 * p] = code; }
                        if (dhi < bd[2 * p + 1]) { bd[2 * p + 1] = dhi; bk[2 * p + 1] = code; }
                    }
                }
            }
        }

        // ---- reduce across 16 tx lanes, then global atomic merge ----
#pragma unroll
        for (int r = 0; r < 8; r++) {
            float d = bd[r];
            int   k = bk[r];
#pragma unroll
            for (int o = 1; o < 16; o <<= 1) {
                float od = __shfl_xor_sync(0xffffffffu, d, o);
                int   ok = __shfl_xor_sync(0xffffffffu, k, o);
                if (od < d || (od == d && ok < k)) { d = od; k = ok; }
            }
            if (tx == 0) {
                unsigned long long key =
                    ((unsigned long long)__float_as_uint(d) << 32) | (unsigned int)k;
                atomicMin(&g_best[row0 + ty * 8 + r], key);
            }
        }
    }
}

// -------- output gather + straight-through + loss partials --------
__global__ void vq_output_kernel(const float* __restrict__ z, const float* __restrict__ cb,
                                 float* __restrict__ out) {
    const int tid = threadIdx.x;
    const size_t g4 = (size_t)blockIdx.x * 256 + tid;
    const int row = (int)(g4 >> 6);
    const int c4 = (int)(g4 & 63);
    const int idx = (int)(g_best[row] & 0xFFFFFFFFULL);

    const float4 zv = reinterpret_cast<const float4*>(z)[g4];
    const float4 qv = reinterpret_cast<const float4*>(cb)[(size_t)idx * 64 + c4];

    float4 o;
    o.x = zv.x + (qv.x - zv.x);
    o.y = zv.y + (qv.y - zv.y);
    o.z = zv.z + (qv.z - zv.z);
    o.w = zv.w + (qv.w - zv.w);
    reinterpret_cast<float4*>(out)[g4] = o;

    const float dx = zv.x - qv.x, dy = zv.y - qv.y, dz = zv.z - qv.z, dw = zv.w - qv.w;
    float part = dx * dx;
    part = fmaf(dy, dy, part);
    part = fmaf(dz, dz, part);
    part = fmaf(dw, dw, part);

    __shared__ float sp[256];
    sp[tid] = part;
    __syncthreads();
#pragma unroll
    for (int s = 128; s; s >>= 1) {
        if (tid < s) sp[tid] += sp[tid + s];
        __syncthreads();
    }
    if (tid == 0) g_partial[blockIdx.x] = sp[0];
}

// -------- deterministic final loss reduction --------
__global__ void vq_loss_kernel(float* __restrict__ out, int out_size) {
    __shared__ double sm[256];
    const int tid = threadIdx.x;
    double s = 0.0;
    for (int i = tid; i < 8192; i += 256) s += (double)g_partial[i];
    sm[tid] = s;
    __syncthreads();
#pragma unroll
    for (int st = 128; st; st >>= 1) {
        if (tid < st) sm[tid] += sm[tid + st];
        __syncthreads();
    }
    if (tid == 0) {
        const float m = (float)(sm[0] / (double)QSIZE);
        const float vq = 0.25f * m + m;
        for (int i = QSIZE; i < out_size; i++) out[i] = vq;
    }
}

extern "C" void kernel_launch(void* const* d_in, const int* in_sizes, int n_in,
                              void* d_out, int out_size) {
    const float* z  = (const float*)d_in[0];
    const float* cb = (const float*)d_in[1];
    if (n_in >= 2 && in_sizes[0] == KCODES * DD && in_sizes[1] == NROWS * DD) {
        const float* t = z; z = cb; cb = t;
    }
    float* out = (float*)d_out;

    const int smem_bytes = (DD * 128 + 2 * KC * 128) * (int)sizeof(float);  // 163840
    cudaFuncSetAttribute(vq_argmin_kernel,
                         cudaFuncAttributeMaxDynamicSharedMemorySize, smem_bytes);

    // fused init + both norms (one launch)
    vq_prep_kernel<<<((NROWS + KCODES) * 32) / 256, 256>>>(z, cb);
    vq_argmin_kernel<<<148, 256, smem_bytes>>>(z, cb);
    vq_output_kernel<<<QSIZE / 1024, 256>>>(z, cb, out);
    vq_loss_kernel<<<1, 256>>>(out, out_size);
}